// round 17
// baseline (speedup 1.0000x reference)
#include <cuda_runtime.h>
#include <cuda_bf16.h>
#include <mma.h>
#include <math.h>

// Problem-fixed capacities
#define NMAX 50000
#define NPAD 50048
#define EMAX 800000
#define SCAN_BLK 256
#define SCAN_GRID ((NMAX + SCAN_BLK - 1) / SCAN_BLK)   // 196

// ---------------- scratch (no allocation allowed) ----------------
__device__ int   g_is64;
__device__ int   g_deg[NMAX];          // zero-initialized; self-cleaned by k_scan
__device__ int   g_cursor[NMAX];
__device__ float g_dinv[NMAX];
__device__ int   g_rowptr[NMAX + 1];
__device__ int   g_col[EMAX];
__device__ int            g_agg[SCAN_GRID];
__device__ volatile unsigned g_flag[SCAN_GRID];   // generation tags (monotonic)
__device__ unsigned g_tick;
__device__ __align__(256) float g_bufA[NPAD * 128];   // GEMM1 out (f32)
__device__ __align__(256) float g_h1[NPAD * 128];     // agg128 out (f32; pad rows stay 0)
__device__ __align__(256) float g_bufB[NPAD * 64];    // GEMM2 out (f32)

// Edge index accessor: handles int32 (JAX x64-disabled) and int64 layouts.
__device__ __forceinline__ int edge_at(const void* ei, long idx, int is64) {
    if (is64) {
        return (int)((const long long*)ei)[idx];
    }
    return ((const int*)ei)[idx];
}

// ---------------- degree count (detect folded in) ----------------
__global__ void k_count(const void* __restrict__ ei, int e) {
    __shared__ int s_is64;
    {
        const long long* p = (const long long*)ei;
        int m = e < 2048 ? e : 2048;
        int ok = 1;
        for (int i = threadIdx.x; i < m; i += blockDim.x) {
            long long v = p[i];
            if (v < 0 || v >= NMAX) {
                ok = 0;
            }
        }
        int all = __syncthreads_and(ok);
        if (threadIdx.x == 0) {
            s_is64 = all;
            g_is64 = all;
        }
        __syncthreads();
    }
    int is64 = s_is64;

    int i4 = (blockIdx.x * blockDim.x + threadIdx.x) * 4;
    if (i4 >= e) {
        return;
    }
    if (!is64 && (e & 3) == 0) {
        const int4* p = (const int4*)((const int*)ei + e);
        int4 d = p[i4 >> 2];
        if (d.x >= 0 && d.x < NMAX) { atomicAdd(&g_deg[d.x], 1); }
        if (d.y >= 0 && d.y < NMAX) { atomicAdd(&g_deg[d.y], 1); }
        if (d.z >= 0 && d.z < NMAX) { atomicAdd(&g_deg[d.z], 1); }
        if (d.w >= 0 && d.w < NMAX) { atomicAdd(&g_deg[d.w], 1); }
    } else {
        int lim = (i4 + 4 < e) ? i4 + 4 : e;
        for (int i = i4; i < lim; i++) {
            int d = edge_at(ei, (long)e + i, is64);
            if (d >= 0 && d < NMAX) { atomicAdd(&g_deg[d], 1); }
        }
    }
}

// ---------------- single-kernel decoupled-lookback scan ----------------
__global__ void k_scan(int n, int e_total) {
    __shared__ int wsum[8];
    __shared__ int s_prev;
    __shared__ unsigned s_gen;
    int blk = blockIdx.x;
    int tid = threadIdx.x;
    int lane = tid & 31;
    int wid = tid >> 5;
    int i = blk * SCAN_BLK + tid;

    if (tid == 0) {
        unsigned t = atomicAdd(&g_tick, 1u);
        s_gen = t / gridDim.x + 1u;
    }

    int v = (i < n) ? g_deg[i] : 0;
    if (i < n) {
        g_dinv[i] = rsqrtf((float)(v + 1));  // +1 self loop
        g_deg[i] = 0;                         // self-clean for next replay
    }

    int incl = v;
    #pragma unroll
    for (int off = 1; off < 32; off <<= 1) {
        int t = __shfl_up_sync(0xffffffffu, incl, off);
        if (lane >= off) { incl += t; }
    }
    if (lane == 31) { wsum[wid] = incl; }
    __syncthreads();
    if (wid == 0 && lane < 8) {
        int ws = wsum[lane];
        int wincl = ws;
        #pragma unroll
        for (int off = 1; off < 8; off <<= 1) {
            int t = __shfl_up_sync(0xffu, wincl, off);
            if (lane >= off) { wincl += t; }
        }
        wsum[lane] = wincl - ws;
        if (lane == 7) {
            g_agg[blk] = wincl;
            __threadfence();
            g_flag[blk] = s_gen;
        }
    }
    __syncthreads();

    if (wid == 0) {
        unsigned gen = s_gen;
        int sum = 0;
        for (int base = 0; base < blk; base += 32) {
            int j = base + lane;
            int a = 0;
            if (j < blk) {
                while (g_flag[j] != gen) { }
                __threadfence();
                a = g_agg[j];
            }
            #pragma unroll
            for (int off = 16; off; off >>= 1) {
                a += __shfl_down_sync(0xffffffffu, a, off);
            }
            if (lane == 0) { sum += a; }
        }
        if (lane == 0) { s_prev = sum; }
    }
    __syncthreads();

    int excl = s_prev + wsum[wid] + incl - v;
    if (i < n) {
        g_rowptr[i] = excl;
        g_cursor[i] = excl;
    }
    if (blk == 0 && tid == 0) {
        g_rowptr[n] = e_total;
    }
}

// ---------------- CSR fill ----------------
__global__ void k_fill(const void* __restrict__ ei, int e) {
    int is64 = g_is64;
    int i4 = (blockIdx.x * blockDim.x + threadIdx.x) * 4;
    if (i4 >= e) {
        return;
    }
    if (!is64 && (e & 3) == 0) {
        const int4* ps = (const int4*)(const int*)ei;
        const int4* pd = (const int4*)((const int*)ei + e);
        int4 s = ps[i4 >> 2];
        int4 d = pd[i4 >> 2];
        int sa[4];
        int da[4];
        sa[0] = s.x; sa[1] = s.y; sa[2] = s.z; sa[3] = s.w;
        da[0] = d.x; da[1] = d.y; da[2] = d.z; da[3] = d.w;
        #pragma unroll
        for (int j = 0; j < 4; j++) {
            int ss = sa[j];
            int dd = da[j];
            if (ss >= 0 && ss < NMAX && dd >= 0 && dd < NMAX) {
                int pos = atomicAdd(&g_cursor[dd], 1);
                if (pos >= 0 && pos < EMAX) {
                    g_col[pos] = ss;
                }
            }
        }
    } else {
        int lim = (i4 + 4 < e) ? i4 + 4 : e;
        for (int i = i4; i < lim; i++) {
            int s = edge_at(ei, i, is64);
            int d = edge_at(ei, (long)e + i, is64);
            if (s >= 0 && s < NMAX && d >= 0 && d < NMAX) {
                int pos = atomicAdd(&g_cursor[d], 1);
                if (pos >= 0 && pos < EMAX) {
                    g_col[pos] = s;
                }
            }
        }
    }
}

// ---------------- smem-staged wmma bf16x3 GEMM, f32 inputs ----------------
// C[.,ND] = Ah@Bh + Ah@Bl + Al@Bh (fp32 acc); hi/lo split in the tile loaders.
// CTA tile 128xND (single n-pass). 8 warps: 4m x 2n, warp tile 32 x ND/2,
// NG = ND/32 16-col fragment groups per warp. Grid: (rows/128). C padded.
template<int ND>
__global__ void __launch_bounds__(256) k_gemm_f32(
    const float* __restrict__ A, const float* __restrict__ B,
    float* __restrict__ C, int M)
{
    using namespace nvcuda;
    const int KD = 128;
    const int AS = 40;        // smem A row stride (bf16 elems)
    const int BS = ND + 8;    // smem B row stride
    const int WN = ND / 2;    // warp n extent
    const int NG = WN / 16;   // 16-col fragments per warp (ND=128 -> 4, ND=64 -> 2)

    __shared__ __align__(16) __nv_bfloat16 sAh[128 * AS];
    __shared__ __align__(16) __nv_bfloat16 sAl[128 * AS];
    __shared__ __align__(16) __nv_bfloat16 sBh[32 * BS];
    __shared__ __align__(16) __nv_bfloat16 sBl[32 * BS];

    int tid = threadIdx.x;
    int wid = tid >> 5;
    int wm = (wid & 3) * 32;
    int wnl = (wid >> 2) * WN;
    int bm = blockIdx.x * 128;

    wmma::fragment<wmma::accumulator, 16, 16, 16, float> c[2][NG];
    #pragma unroll
    for (int i = 0; i < 2; i++) {
        #pragma unroll
        for (int j = 0; j < NG; j++) {
            wmma::fill_fragment(c[i][j], 0.0f);
        }
    }

    for (int k0 = 0; k0 < KD; k0 += 32) {
        // A tile: 128 rows x 32 cols; convert f32 -> hi/lo in-loader
        #pragma unroll
        for (int it = 0; it < 2; it++) {
            int f = tid + it * 256;
            int row = f >> 2;
            int cc = f & 3;
            int gm = bm + row;
            float4 v0 = make_float4(0.f, 0.f, 0.f, 0.f);
            float4 v1 = make_float4(0.f, 0.f, 0.f, 0.f);
            if (gm < M) {
                v0 = *(const float4*)&A[(long)gm * KD + k0 + 8 * cc];
                v1 = *(const float4*)&A[(long)gm * KD + k0 + 8 * cc + 4];
            }
            float vv[8];
            vv[0] = v0.x; vv[1] = v0.y; vv[2] = v0.z; vv[3] = v0.w;
            vv[4] = v1.x; vv[5] = v1.y; vv[6] = v1.z; vv[7] = v1.w;
            alignas(16) __nv_bfloat16 hh[8];
            alignas(16) __nv_bfloat16 ll[8];
            #pragma unroll
            for (int j = 0; j < 8; j++) {
                __nv_bfloat16 h = __float2bfloat16(vv[j]);
                hh[j] = h;
                ll[j] = __float2bfloat16(vv[j] - __bfloat162float(h));
            }
            *(uint4*)&sAh[row * AS + 8 * cc] = *(const uint4*)hh;
            *(uint4*)&sAl[row * AS + 8 * cc] = *(const uint4*)ll;
        }
        // B tile: 32 rows x ND cols
        #pragma unroll
        for (int f = tid; f < 32 * ND / 8; f += 256) {
            int row = f / (ND / 8);
            int cc = f % (ND / 8);
            long gidx = (long)(k0 + row) * ND + 8 * cc;
            float4 v0 = *(const float4*)&B[gidx];
            float4 v1 = *(const float4*)&B[gidx + 4];
            float vv[8];
            vv[0] = v0.x; vv[1] = v0.y; vv[2] = v0.z; vv[3] = v0.w;
            vv[4] = v1.x; vv[5] = v1.y; vv[6] = v1.z; vv[7] = v1.w;
            alignas(16) __nv_bfloat16 hh[8];
            alignas(16) __nv_bfloat16 ll[8];
            #pragma unroll
            for (int j = 0; j < 8; j++) {
                __nv_bfloat16 h = __float2bfloat16(vv[j]);
                hh[j] = h;
                ll[j] = __float2bfloat16(vv[j] - __bfloat162float(h));
            }
            *(uint4*)&sBh[row * BS + 8 * cc] = *(const uint4*)hh;
            *(uint4*)&sBl[row * BS + 8 * cc] = *(const uint4*)ll;
        }
        __syncthreads();

        #pragma unroll
        for (int ks = 0; ks < 32; ks += 16) {
            wmma::fragment<wmma::matrix_a, 16, 16, 16, __nv_bfloat16, wmma::row_major> ah[2];
            wmma::fragment<wmma::matrix_a, 16, 16, 16, __nv_bfloat16, wmma::row_major> al[2];
            #pragma unroll
            for (int i = 0; i < 2; i++) {
                wmma::load_matrix_sync(ah[i], &sAh[(wm + 16 * i) * AS + ks], AS);
                wmma::load_matrix_sync(al[i], &sAl[(wm + 16 * i) * AS + ks], AS);
            }
            #pragma unroll
            for (int j = 0; j < NG; j++) {
                wmma::fragment<wmma::matrix_b, 16, 16, 16, __nv_bfloat16, wmma::row_major> bh;
                wmma::fragment<wmma::matrix_b, 16, 16, 16, __nv_bfloat16, wmma::row_major> bl;
                wmma::load_matrix_sync(bh, &sBh[ks * BS + wnl + 16 * j], BS);
                wmma::load_matrix_sync(bl, &sBl[ks * BS + wnl + 16 * j], BS);
                #pragma unroll
                for (int i = 0; i < 2; i++) {
                    wmma::mma_sync(c[i][j], ah[i], bh, c[i][j]);
                    wmma::mma_sync(c[i][j], ah[i], bl, c[i][j]);
                    wmma::mma_sync(c[i][j], al[i], bh, c[i][j]);
                }
            }
        }
        __syncthreads();
    }

    #pragma unroll
    for (int i = 0; i < 2; i++) {
        #pragma unroll
        for (int j = 0; j < NG; j++) {
            wmma::store_matrix_sync(C + (long)(bm + wm + 16 * i) * ND + wnl + 16 * j,
                                    c[i][j], ND, wmma::mem_row_major);
        }
    }
}

// ---------------- layer-1 aggregation (F=128, dinv[src]-weighted) -> f32 h1 ----------------
__global__ void __launch_bounds__(256) k_agg128(const float* __restrict__ h,
                                                const float* __restrict__ bias,
                                                float* __restrict__ out, int n) {
    int node = blockIdx.x * 8 + (threadIdx.x >> 5);
    if (node >= n) {
        return;
    }
    int lane = threadIdx.x & 31;
    const float4* hv = (const float4*)h;
    float di = g_dinv[node];
    float4 a = __ldg(&hv[(long)node * 32 + lane]);
    float4 acc;
    acc.x = di * a.x;
    acc.y = di * a.y;
    acc.z = di * a.z;
    acc.w = di * a.w;
    int beg = g_rowptr[node];
    int end = g_rowptr[node + 1];
    #pragma unroll 4
    for (int p = beg; p < end; p++) {
        int s = g_col[p];
        float ws = g_dinv[s];
        float4 v = __ldg(&hv[(long)s * 32 + lane]);
        acc.x += ws * v.x;
        acc.y += ws * v.y;
        acc.z += ws * v.z;
        acc.w += ws * v.w;
    }
    float4 b = __ldg(&((const float4*)bias)[lane]);
    float4 r;
    r.x = tanhf(di * acc.x + b.x);
    r.y = tanhf(di * acc.y + b.y);
    r.z = tanhf(di * acc.z + b.z);
    r.w = tanhf(di * acc.w + b.w);
    ((float4*)out)[(long)node * 32 + lane] = r;
}

// ---------------- fused agg(F=64, dinv[src]-weighted) + MLP head ----------------
__global__ void __launch_bounds__(256) k_agg64_mlp(const float* __restrict__ h,
                                                   const float* __restrict__ b2,
                                                   const float* __restrict__ Wf1,
                                                   const float* __restrict__ bf1,
                                                   const float* __restrict__ Wf2,
                                                   const float* __restrict__ bf2,
                                                   float* __restrict__ out, int n) {
    __shared__ float sW[64 * 32];
    __shared__ float sb1[32];
    __shared__ float sW2[32];
    __shared__ float sb2;
    __shared__ float stage[8][64];
    for (int i = threadIdx.x; i < 64 * 32; i += blockDim.x) {
        sW[i] = Wf1[i];
    }
    if (threadIdx.x < 32) {
        sb1[threadIdx.x] = bf1[threadIdx.x];
        sW2[threadIdx.x] = Wf2[threadIdx.x];
    }
    if (threadIdx.x == 0) {
        sb2 = bf2[0];
    }
    __syncthreads();

    int w = threadIdx.x >> 5;
    int node = blockIdx.x * 8 + w;
    if (node >= n) {
        return;
    }
    int lane = threadIdx.x & 31;

    const float2* hv = (const float2*)h;
    float di = g_dinv[node];
    float2 a = __ldg(&hv[(long)node * 32 + lane]);
    float2 acc;
    acc.x = di * a.x;
    acc.y = di * a.y;
    int beg = g_rowptr[node];
    int end = g_rowptr[node + 1];
    #pragma unroll 4
    for (int p = beg; p < end; p++) {
        int s = g_col[p];
        float ws = g_dinv[s];
        float2 v = __ldg(&hv[(long)s * 32 + lane]);
        acc.x += ws * v.x;
        acc.y += ws * v.y;
    }
    float2 bb = __ldg(&((const float2*)b2)[lane]);
    stage[w][2 * lane]     = tanhf(di * acc.x + bb.x);
    stage[w][2 * lane + 1] = tanhf(di * acc.y + bb.y);
    __syncwarp();

    float a1 = sb1[lane];
    #pragma unroll
    for (int j = 0; j < 64; j++) {
        a1 += stage[w][j] * sW[j * 32 + lane];
    }
    float t = tanhf(a1);
    float y = t * sW2[lane];
    #pragma unroll
    for (int off = 16; off; off >>= 1) {
        y += __shfl_down_sync(0xffffffffu, y, off);
    }
    if (lane == 0) {
        out[node] = y + sb2;
    }
}

// ---------------- launch ----------------
extern "C" void kernel_launch(void* const* d_in, const int* in_sizes, int n_in,
                              void* d_out, int out_size) {
    const float* x   = (const float*)d_in[0];
    const void*  ei  = d_in[1];
    const float* W1  = (const float*)d_in[2];
    const float* b1  = (const float*)d_in[3];
    const float* W2  = (const float*)d_in[4];
    const float* b2  = (const float*)d_in[5];
    const float* Wf1 = (const float*)d_in[6];
    const float* bf1 = (const float*)d_in[7];
    const float* Wf2 = (const float*)d_in[8];
    const float* bf2 = (const float*)d_in[9];
    float* out = (float*)d_out;

    int n = in_sizes[0] / 128;   // 50000
    int e = in_sizes[1] / 2;     // 800000

    float* bufA = 0;
    float* h1 = 0;
    float* bufB = 0;
    cudaGetSymbolAddress((void**)&bufA, g_bufA);
    cudaGetSymbolAddress((void**)&h1, g_h1);
    cudaGetSymbolAddress((void**)&bufB, g_bufB);

    static cudaStream_t sB = 0;
    static cudaEvent_t evFork = 0;
    static cudaEvent_t evJoin = 0;
    if (sB == 0) {
        cudaStreamCreateWithFlags(&sB, cudaStreamNonBlocking);
        cudaEventCreateWithFlags(&evFork, cudaEventDisableTiming);
        cudaEventCreateWithFlags(&evJoin, cudaEventDisableTiming);
    }

    int ge4 = (e + 1023) / 1024;
    int gw  = (n + 7) / 8;
    int gm  = (n + 127) / 128;   // 391, NPAD covers gm*128 rows

    // Fork: 3-launch CSR build on side stream (independent of GEMM path)
    cudaEventRecord(evFork, 0);
    cudaStreamWaitEvent(sB, evFork, 0);

    k_count<<<ge4, 256, 0, sB>>>(ei, e);
    k_scan<<<SCAN_GRID, SCAN_BLK, 0, sB>>>(n, e);
    k_fill<<<ge4, 256, 0, sB>>>(ei, e);
    cudaEventRecord(evJoin, sB);

    // Main stream: GEMM1 single n-pass (graph-independent)
    k_gemm_f32<128><<<gm, 256>>>(x, W1, bufA, n);

    // Join: aggregation needs CSR + dinv
    cudaStreamWaitEvent(0, evJoin, 0);
    k_agg128<<<gw, 256>>>(bufA, b1, h1, n);

    // Layer 2: GEMM (h1 padded, pad rows stay zero) + fused agg64 + MLP head
    k_gemm_f32<64><<<gm, 256>>>(h1, W2, bufB, NPAD);
    k_agg64_mlp<<<gw, 256>>>(bufB, b2, Wf1, bf1, Wf2, bf2, out, n);
}